// round 1
// baseline (speedup 1.0000x reference)
#include <cuda_runtime.h>
#include <math.h>

static constexpr int   Nn        = 50000;
static constexpr int   Ee        = 800000;
static constexpr int   ET        = Nn + Ee;       // edges + self loops
static constexpr int   Cc        = 256;           // HEADS*OUT_C
static constexpr int   Hh        = 8;
static constexpr float NEG_SLOPE = 0.2f;
static constexpr float BN_EPS    = 1e-5f;

// -------- device scratch (static: no allocation allowed) --------
__device__ float    g_h[(size_t)Nn * Cc];      // projected features  (51.2 MB)
__device__ float    g_asrc[Nn * Hh];
__device__ float    g_adst[Nn * Hh];
__device__ float    g_logit[(size_t)ET * Hh];  // leaky-relu logits   (27.2 MB)
__device__ unsigned g_max[Nn * Hh];            // order-encoded float max
__device__ float    g_sum[Nn * Hh];            // softmax denominators
__device__ double   g_colsum[Cc];
__device__ double   g_colsq[Cc];
__device__ double   g_easum;
__device__ float    g_ecoef[Hh];               // sum_c W_edge[h,c]*att_edge[h,c]
__device__ float    g_eamean;

// monotone float<->uint encoding for atomicMax on floats
__device__ __forceinline__ unsigned fenc(float v) {
    unsigned u = __float_as_uint(v);
    return u ^ (unsigned)(((int)u >> 31) | 0x80000000);
}
__device__ __forceinline__ float fdec(unsigned e) {
    unsigned u = (e & 0x80000000u) ? (e ^ 0x80000000u) : ~e;
    return __uint_as_float(u);
}

// -------- K0: zero all accumulators (fresh every call: determinism) --------
__global__ void k_init(float* __restrict__ out) {
    int i = blockIdx.x * blockDim.x + threadIdx.x;
    if (i < Nn * Cc) out[i] = 0.f;
    if (i < Nn * Hh) { g_sum[i] = 0.f; g_max[i] = 0u; }
    if (i < Cc) { g_colsum[i] = 0.0; g_colsq[i] = 0.0; }
    if (i == 0) g_easum = 0.0;
}

// -------- K1: h = x @ W, fused a_src/a_dst epilogue --------
// Block = 32 rows x 256 cols. Thread j owns output column j for 32 rows.
// Warp w == head w (columns 32w..32w+31), so the per-head attention dot
// reduces with a plain warp shuffle.
__global__ void __launch_bounds__(256) k_gemm(
    const float* __restrict__ x, const float* __restrict__ W,
    const float* __restrict__ att_src, const float* __restrict__ att_dst)
{
    __shared__ float xs[32][Cc];
    const int row0 = blockIdx.x * 32;
    const int j = threadIdx.x;

    for (int i = j; i < 32 * (Cc / 4); i += 256) {
        int m = i >> 6, q = i & 63;
        int row = row0 + m;
        float4 v = make_float4(0.f, 0.f, 0.f, 0.f);
        if (row < Nn) v = ((const float4*)x)[(size_t)row * (Cc / 4) + q];
        ((float4*)xs[m])[q] = v;
    }
    __syncthreads();

    float acc[32];
#pragma unroll
    for (int m = 0; m < 32; m++) acc[m] = 0.f;

#pragma unroll 2
    for (int k = 0; k < Cc; k += 4) {
        float w0 = W[(k + 0) * Cc + j];
        float w1 = W[(k + 1) * Cc + j];
        float w2 = W[(k + 2) * Cc + j];
        float w3 = W[(k + 3) * Cc + j];
#pragma unroll
        for (int m = 0; m < 32; m++) {
            float4 xv = *(const float4*)&xs[m][k];   // uniform (broadcast) LDS.128
            acc[m] = fmaf(xv.x, w0, fmaf(xv.y, w1, fmaf(xv.z, w2, fmaf(xv.w, w3, acc[m]))));
        }
    }

    const int head = j >> 5, lane = j & 31;
    const float aw = att_src[j], dw = att_dst[j];
#pragma unroll 1
    for (int m = 0; m < 32; m++) {
        int row = row0 + m;
        if (row >= Nn) break;                        // uniform across warp
        g_h[(size_t)row * Cc + j] = acc[m];
        float s = acc[m] * aw, d = acc[m] * dw;
#pragma unroll
        for (int off = 16; off; off >>= 1) {
            s += __shfl_down_sync(0xffffffffu, s, off);
            d += __shfl_down_sync(0xffffffffu, d, off);
        }
        if (lane == 0) {
            g_asrc[row * Hh + head] = s;
            g_adst[row * Hh + head] = d;
        }
    }
}

// -------- K2: mean(edge_attr) reduction --------
__global__ void k_easum(const float* __restrict__ ea) {
    __shared__ double sh[256];
    double s = 0.0;
    for (int i = blockIdx.x * blockDim.x + threadIdx.x; i < Ee;
         i += gridDim.x * blockDim.x)
        s += (double)ea[i];
    sh[threadIdx.x] = s;
    __syncthreads();
    for (int o = 128; o; o >>= 1) {
        if (threadIdx.x < o) sh[threadIdx.x] += sh[threadIdx.x + o];
        __syncthreads();
    }
    if (threadIdx.x == 0) atomicAdd(&g_easum, sh[0]);
}

// -------- K3: per-head edge coefficient + ea mean scalar --------
__global__ void k_ecoef(const float* __restrict__ W_edge,
                        const float* __restrict__ att_edge) {
    int j = threadIdx.x;   // 256 threads
    float p = W_edge[j] * att_edge[j];
    for (int off = 16; off; off >>= 1) p += __shfl_down_sync(0xffffffffu, p, off);
    if ((j & 31) == 0) g_ecoef[j >> 5] = p;
    if (j == 0) g_eamean = (float)(g_easum / (double)Ee);
}

// -------- K4: logits + segment max (thread per edge-head) --------
__global__ void __launch_bounds__(256) k_logit(const int* __restrict__ ei,
                                               const float* __restrict__ ea) {
    int i = blockIdx.x * blockDim.x + threadIdx.x;
    if (i >= ET * Hh) return;
    int e = i >> 3, h = i & 7;
    int s, d; float a;
    if (e < Ee) { s = ei[e]; d = ei[Ee + e]; a = ea[e]; }
    else        { s = d = e - Ee; a = g_eamean; }
    float v = g_asrc[s * Hh + h] + g_adst[d * Hh + h] + a * g_ecoef[h];
    v = v > 0.f ? v : NEG_SLOPE * v;
    g_logit[i] = v;
    atomicMax(&g_max[d * Hh + h], fenc(v));
}

// -------- K5: exp + denominator + UNNORMALIZED aggregation (warp/edge) --------
// out[dst] += exp(l - max[dst]) * h[src]; division by sum folded into K6/K7.
__global__ void __launch_bounds__(256) k_agg(const int* __restrict__ ei,
                                             float* __restrict__ out) {
    int e = blockIdx.x * 8 + (threadIdx.x >> 5);
    if (e >= ET) return;
    int lane = threadIdx.x & 31;
    int s, d;
    if (e < Ee) { s = ei[e]; d = ei[Ee + e]; }
    else        { s = d = e - Ee; }

    float w = 0.f;
    if (lane < Hh) {
        float l = g_logit[e * Hh + lane];
        float mx = fdec(g_max[d * Hh + lane]);
        w = __expf(l - mx);
        atomicAdd(&g_sum[d * Hh + lane], w);
    }
    const float* hr = &g_h[(size_t)s * Cc];
    float* orow = &out[(size_t)d * Cc];
#pragma unroll
    for (int h = 0; h < Hh; h++) {
        float wh = __shfl_sync(0xffffffffu, w, h);
        atomicAdd(&orow[h * 32 + lane], wh * hr[h * 32 + lane]);
    }
}

// -------- K6: per-column BN statistics on normalized values --------
__global__ void __launch_bounds__(256) k_stats(const float* __restrict__ out) {
    int c = threadIdx.x, h = c >> 5;
    int r0 = blockIdx.x * 128;
    int rend = min(r0 + 128, Nn);
    double s = 0.0, q = 0.0;
    for (int n = r0; n < rend; n++) {
        float v = out[(size_t)n * Cc + c] / (g_sum[n * Hh + h] + 1e-16f);
        s += (double)v;
        q += (double)v * (double)v;
    }
    atomicAdd(&g_colsum[c], s);
    atomicAdd(&g_colsq[c], q);
}

// -------- K7: softmax-normalize + BatchNorm + ELU (bias cancels in BN) -----
__global__ void __launch_bounds__(256) k_final(float* __restrict__ out,
                                               const float* __restrict__ gamma,
                                               const float* __restrict__ beta) {
    int i = blockIdx.x * blockDim.x + threadIdx.x;
    if (i >= Nn * Cc) return;
    int c = i & (Cc - 1);
    int n = i >> 8;
    int h = c >> 5;
    float v = out[i] / (g_sum[n * Hh + h] + 1e-16f);
    float mean = (float)(g_colsum[c] / (double)Nn);
    float var = (float)(g_colsq[c] / (double)Nn) - mean * mean;
    float y = (v - mean) * rsqrtf(var + BN_EPS) * gamma[c] + beta[c];
    out[i] = y > 0.f ? y : expm1f(y);
}

extern "C" void kernel_launch(void* const* d_in, const int* in_sizes, int n_in,
                              void* d_out, int out_size) {
    const float* x        = (const float*)d_in[0];
    const int*   ei       = (const int*)d_in[1];
    const float* ea       = (const float*)d_in[2];
    const float* W        = (const float*)d_in[3];
    const float* att_src  = (const float*)d_in[4];
    const float* att_dst  = (const float*)d_in[5];
    const float* W_edge   = (const float*)d_in[6];
    const float* att_edge = (const float*)d_in[7];
    // d_in[8] = bias : cancels exactly through BatchNorm mean subtraction
    const float* gamma    = (const float*)d_in[9];
    const float* beta     = (const float*)d_in[10];
    float* out = (float*)d_out;

    k_init <<<(Nn * Cc + 255) / 256, 256>>>(out);
    k_gemm <<<(Nn + 31) / 32, 256>>>(x, W, att_src, att_dst);
    k_easum<<<512, 256>>>(ea);
    k_ecoef<<<1, 256>>>(W_edge, att_edge);
    k_logit<<<(ET * Hh + 255) / 256, 256>>>(ei, ea);
    k_agg  <<<(ET + 7) / 8, 256>>>(ei, out);
    k_stats<<<(Nn + 127) / 128, 256>>>(out);
    k_final<<<(Nn * Cc + 255) / 256, 256>>>(out, gamma, beta);
}

// round 2
// speedup vs baseline: 1.2010x; 1.2010x over previous
#include <cuda_runtime.h>
#include <math.h>

static constexpr int   Nn        = 50000;
static constexpr int   Ee        = 800000;
static constexpr int   ET        = Nn + Ee;       // edges + self loops
static constexpr int   Cc        = 256;           // HEADS*OUT_C
static constexpr int   Hh        = 8;
static constexpr float NEG_SLOPE = 0.2f;
static constexpr float BN_EPS    = 1e-5f;

// -------- device scratch (static: no allocation allowed) --------
__device__ float    g_h[(size_t)Nn * Cc];        // projected features (51.2 MB)
__device__ float    g_asrc[Nn * Hh];
__device__ float    g_adst[Nn * Hh];
__device__ int      g_deg[Nn];
__device__ int      g_cursor[Nn];
__device__ int      g_rowstart[Nn + 1];
__device__ int      g_csr_src[ET];
__device__ float    g_csr_logit[(size_t)ET * Hh]; // CSR-ordered logits (27.2 MB)
__device__ double   g_colsum[Cc];
__device__ double   g_colsq[Cc];
__device__ double   g_easum;
__device__ float    g_ecoef[Hh];                 // sum_c W_edge[h,c]*att_edge[h,c]
__device__ float    g_eamean;

__device__ __forceinline__ float lrelu(float v) {
    return v > 0.f ? v : NEG_SLOPE * v;
}

// -------- K0: zero the small accumulators (fresh every call) --------
__global__ void k_init() {
    int i = blockIdx.x * blockDim.x + threadIdx.x;
    if (i < Nn) { g_deg[i] = 0; g_cursor[i] = 0; }
    if (i < Cc) { g_colsum[i] = 0.0; g_colsq[i] = 0.0; }
    if (i == 0) g_easum = 0.0;
}

// -------- K1: h = x @ W, fused a_src/a_dst epilogue --------
__global__ void __launch_bounds__(256) k_gemm(
    const float* __restrict__ x, const float* __restrict__ W,
    const float* __restrict__ att_src, const float* __restrict__ att_dst)
{
    __shared__ float xs[32][Cc];
    const int row0 = blockIdx.x * 32;
    const int j = threadIdx.x;

    for (int i = j; i < 32 * (Cc / 4); i += 256) {
        int m = i >> 6, q = i & 63;
        int row = row0 + m;
        float4 v = make_float4(0.f, 0.f, 0.f, 0.f);
        if (row < Nn) v = ((const float4*)x)[(size_t)row * (Cc / 4) + q];
        ((float4*)xs[m])[q] = v;
    }
    __syncthreads();

    float acc[32];
#pragma unroll
    for (int m = 0; m < 32; m++) acc[m] = 0.f;

#pragma unroll 2
    for (int k = 0; k < Cc; k += 4) {
        float w0 = W[(k + 0) * Cc + j];
        float w1 = W[(k + 1) * Cc + j];
        float w2 = W[(k + 2) * Cc + j];
        float w3 = W[(k + 3) * Cc + j];
#pragma unroll
        for (int m = 0; m < 32; m++) {
            float4 xv = *(const float4*)&xs[m][k];
            acc[m] = fmaf(xv.x, w0, fmaf(xv.y, w1, fmaf(xv.z, w2, fmaf(xv.w, w3, acc[m]))));
        }
    }

    const int head = j >> 5, lane = j & 31;
    const float aw = att_src[j], dw = att_dst[j];
#pragma unroll 1
    for (int m = 0; m < 32; m++) {
        int row = row0 + m;
        if (row >= Nn) break;
        g_h[(size_t)row * Cc + j] = acc[m];
        float s = acc[m] * aw, d = acc[m] * dw;
#pragma unroll
        for (int off = 16; off; off >>= 1) {
            s += __shfl_down_sync(0xffffffffu, s, off);
            d += __shfl_down_sync(0xffffffffu, d, off);
        }
        if (lane == 0) {
            g_asrc[row * Hh + head] = s;
            g_adst[row * Hh + head] = d;
        }
    }
}

// -------- K2: mean(edge_attr) reduction --------
__global__ void k_easum(const float* __restrict__ ea) {
    __shared__ double sh[256];
    double s = 0.0;
    for (int i = blockIdx.x * blockDim.x + threadIdx.x; i < Ee;
         i += gridDim.x * blockDim.x)
        s += (double)ea[i];
    sh[threadIdx.x] = s;
    __syncthreads();
    for (int o = 128; o; o >>= 1) {
        if (threadIdx.x < o) sh[threadIdx.x] += sh[threadIdx.x + o];
        __syncthreads();
    }
    if (threadIdx.x == 0) atomicAdd(&g_easum, sh[0]);
}

// -------- K3: per-head edge coefficient + ea mean scalar --------
__global__ void k_ecoef(const float* __restrict__ W_edge,
                        const float* __restrict__ att_edge) {
    int j = threadIdx.x;   // 256 threads
    float p = W_edge[j] * att_edge[j];
    for (int off = 16; off; off >>= 1) p += __shfl_down_sync(0xffffffffu, p, off);
    if ((j & 31) == 0) g_ecoef[j >> 5] = p;
    if (j == 0) g_eamean = (float)(g_easum / (double)Ee);
}

// -------- K4: destination-degree histogram --------
__global__ void __launch_bounds__(256) k_hist(const int* __restrict__ ei) {
    int e = blockIdx.x * blockDim.x + threadIdx.x;
    if (e >= ET) return;
    int d = (e < Ee) ? ei[Ee + e] : e - Ee;
    atomicAdd(&g_deg[d], 1);
}

// -------- K5: exclusive scan of degrees (single block) --------
__global__ void __launch_bounds__(1024) k_scan() {
    __shared__ int sh[1024];
    const int CH = (Nn + 1023) / 1024;   // 49
    int t = threadIdx.x;
    int base = t * CH;
    int s = 0;
    for (int i = 0; i < CH; i++) {
        int idx = base + i;
        if (idx < Nn) s += g_deg[idx];
    }
    sh[t] = s;
    __syncthreads();
    for (int o = 1; o < 1024; o <<= 1) {
        int v = (t >= o) ? sh[t - o] : 0;
        __syncthreads();
        sh[t] += v;
        __syncthreads();
    }
    int run = (t == 0) ? 0 : sh[t - 1];
    for (int i = 0; i < CH; i++) {
        int idx = base + i;
        if (idx < Nn) { g_rowstart[idx] = run; run += g_deg[idx]; }
    }
    if (t == 1023) g_rowstart[Nn] = ET;
}

// -------- K6: scatter edges into CSR + compute logits in CSR order --------
__global__ void __launch_bounds__(256) k_scatter(const int* __restrict__ ei,
                                                 const float* __restrict__ ea) {
    int e = blockIdx.x * blockDim.x + threadIdx.x;
    if (e >= ET) return;
    int s, d; float a;
    if (e < Ee) { s = ei[e]; d = ei[Ee + e]; a = ea[e]; }
    else        { s = d = e - Ee; a = g_eamean; }
    int pos = g_rowstart[d] + atomicAdd(&g_cursor[d], 1);
    g_csr_src[pos] = s;

    float4 as0 = *(const float4*)&g_asrc[s * Hh];
    float4 as1 = *(const float4*)&g_asrc[s * Hh + 4];
    float4 ad0 = *(const float4*)&g_adst[d * Hh];
    float4 ad1 = *(const float4*)&g_adst[d * Hh + 4];
    float4 o0, o1;
    o0.x = lrelu(as0.x + ad0.x + a * g_ecoef[0]);
    o0.y = lrelu(as0.y + ad0.y + a * g_ecoef[1]);
    o0.z = lrelu(as0.z + ad0.z + a * g_ecoef[2]);
    o0.w = lrelu(as0.w + ad0.w + a * g_ecoef[3]);
    o1.x = lrelu(as1.x + ad1.x + a * g_ecoef[4]);
    o1.y = lrelu(as1.y + ad1.y + a * g_ecoef[5]);
    o1.z = lrelu(as1.z + ad1.z + a * g_ecoef[6]);
    o1.w = lrelu(as1.w + ad1.w + a * g_ecoef[7]);
    *(float4*)&g_csr_logit[(size_t)pos * Hh]     = o0;
    *(float4*)&g_csr_logit[(size_t)pos * Hh + 4] = o1;
}

// -------- K7: warp-per-node softmax + aggregation, NO atomics --------
// Pass 1: segment max per head (4 edges x 8 heads per warp iteration).
// Pass 2: acc[cols lane*8..lane*8+7] += exp(l-max) * h[src], sum per head.
// Epilogue: normalize by softmax sum, single coalesced row write.
__global__ void __launch_bounds__(256) k_agg(float* __restrict__ out) {
    int node = (blockIdx.x * 256 + threadIdx.x) >> 5;
    if (node >= Nn) return;
    int lane = threadIdx.x & 31;
    int beg = g_rowstart[node];
    int end = g_rowstart[node + 1];

    // pass 1: per-head max
    float mx = -1e30f;
    int h8 = lane & 7;
    for (int p = beg + (lane >> 3); p < end; p += 4)
        mx = fmaxf(mx, g_csr_logit[(size_t)p * Hh + h8]);
    mx = fmaxf(mx, __shfl_xor_sync(0xffffffffu, mx, 8));
    mx = fmaxf(mx, __shfl_xor_sync(0xffffffffu, mx, 16));
    // now every lane holds max for head (lane & 7)

    // pass 2: weighted accumulation; lane owns columns [lane*8, lane*8+8)
    const int head = lane >> 2;       // head of this lane's 8 columns
    float4 accA = make_float4(0.f, 0.f, 0.f, 0.f);
    float4 accB = make_float4(0.f, 0.f, 0.f, 0.f);
    float wsum = 0.f;

    int s_next = g_csr_src[beg];
    for (int p = beg; p < end; p++) {
        int s = s_next;
        if (p + 1 < end) s_next = g_csr_src[p + 1];
        float l = (lane < 8) ? g_csr_logit[(size_t)p * Hh + lane] : 0.f;
        float w = __expf(l - mx);     // valid on lanes 0..7
        wsum += w;
        float wh = __shfl_sync(0xffffffffu, w, head);
        const float4* hr = (const float4*)&g_h[(size_t)s * Cc + lane * 8];
        float4 v0 = hr[0], v1 = hr[1];
        accA.x += wh * v0.x; accA.y += wh * v0.y;
        accA.z += wh * v0.z; accA.w += wh * v0.w;
        accB.x += wh * v1.x; accB.y += wh * v1.y;
        accB.z += wh * v1.z; accB.w += wh * v1.w;
    }

    float inv = 1.f / (wsum + 1e-16f);            // valid on lanes 0..7
    float invh = __shfl_sync(0xffffffffu, inv, head);
    accA.x *= invh; accA.y *= invh; accA.z *= invh; accA.w *= invh;
    accB.x *= invh; accB.y *= invh; accB.z *= invh; accB.w *= invh;

    float4* orow = (float4*)&out[(size_t)node * Cc + lane * 8];
    orow[0] = accA;
    orow[1] = accB;
}

// -------- K8: per-column BN statistics --------
__global__ void __launch_bounds__(256) k_stats(const float* __restrict__ out) {
    int c = threadIdx.x;
    int r0 = blockIdx.x * 128;
    int rend = min(r0 + 128, Nn);
    double s = 0.0, q = 0.0;
    for (int n = r0; n < rend; n++) {
        float v = out[(size_t)n * Cc + c];
        s += (double)v;
        q += (double)v * (double)v;
    }
    atomicAdd(&g_colsum[c], s);
    atomicAdd(&g_colsq[c], q);
}

// -------- K9: BatchNorm + ELU (bias cancels in BN) --------
__global__ void __launch_bounds__(256) k_final(float* __restrict__ out,
                                               const float* __restrict__ gamma,
                                               const float* __restrict__ beta) {
    int i = blockIdx.x * blockDim.x + threadIdx.x;
    if (i >= Nn * Cc) return;
    int c = i & (Cc - 1);
    float v = out[i];
    float mean = (float)(g_colsum[c] / (double)Nn);
    float var = (float)(g_colsq[c] / (double)Nn) - mean * mean;
    float y = (v - mean) * rsqrtf(var + BN_EPS) * gamma[c] + beta[c];
    out[i] = y > 0.f ? y : expm1f(y);
}

extern "C" void kernel_launch(void* const* d_in, const int* in_sizes, int n_in,
                              void* d_out, int out_size) {
    const float* x        = (const float*)d_in[0];
    const int*   ei       = (const int*)d_in[1];
    const float* ea       = (const float*)d_in[2];
    const float* W        = (const float*)d_in[3];
    const float* att_src  = (const float*)d_in[4];
    const float* att_dst  = (const float*)d_in[5];
    const float* W_edge   = (const float*)d_in[6];
    const float* att_edge = (const float*)d_in[7];
    // d_in[8] = bias : cancels exactly through BatchNorm mean subtraction
    const float* gamma    = (const float*)d_in[9];
    const float* beta     = (const float*)d_in[10];
    float* out = (float*)d_out;

    k_init   <<<(Nn + 255) / 256, 256>>>();
    k_gemm   <<<(Nn + 31) / 32, 256>>>(x, W, att_src, att_dst);
    k_easum  <<<512, 256>>>(ea);
    k_ecoef  <<<1, 256>>>(W_edge, att_edge);
    k_hist   <<<(ET + 255) / 256, 256>>>(ei);
    k_scan   <<<1, 1024>>>();
    k_scatter<<<(ET + 255) / 256, 256>>>(ei, ea);
    k_agg    <<<(Nn * 32 + 255) / 256, 256>>>(out);
    k_stats  <<<(Nn + 127) / 128, 256>>>(out);
    k_final  <<<(Nn * Cc + 255) / 256, 256>>>(out, gamma, beta);
}